// round 1
// baseline (speedup 1.0000x reference)
#include <cuda_runtime.h>
#include <math.h>

// GNN on complete per-scene digraphs: B=64 scenes, N=128 nodes.
// Complete-graph identity: segment_mean over in-edges of node d
//   = (scene_sum(h) - h[d]) / 127.
// Edge layer: sum_{s!=d}(info_s - info_d)[:5]/127 = (S5 - 128*info_d)/127.
// => whole model is per-scene colsums + tiny dense layers. One CTA per scene.

#define NODES   128
#define SCENES  64
#define THREADS 256
#define STRIDE  77          // row pitch (coprime with 32 banks -> conflict-free col reads)
#define INV127  (1.0f/127.0f)

// smem layout (floats)
#define S_W1   0            // 5*64
#define S_B1   320          // 64
#define S_W2   384          // 75*64
#define S_B2   5184         // 64
#define S_W3   5248         // 64*32
#define S_B3   7296         // 32
#define S_W4   7328         // 32*16
#define S_B4   7840         // 16
#define S_WN   7856         // 16*2
#define S_BN   7888         // 2 (+2 pad)
#define S_WG1  7892         // 16*8
#define S_BG1  8020         // 8
#define S_WG2  8028         // 8
#define S_BG2  8036         // 1 (+3 pad)
#define S_A    8040         // 128*77 buffer A (h75: h1 cols 0..63, info cols 64..74)
#define S_BUF  (S_A + NODES*STRIDE)      // 17896: buffer B
#define S_CS   (S_BUF + NODES*STRIDE)    // 27752: column sums (80)
#define S_PART (S_CS + 80)               // 27832: partials 8*80
#define S_TOT  (S_PART + 640)            // 28472 floats
#define SMEM_BYTES (S_TOT * 4)           // 113888 B

// two-stage column sum over 128 rows of C columns starting at 'off' in buffer S.
// All 256 threads must call.
template<int C>
__device__ __forceinline__ void colsum(const float* __restrict__ S, int off,
                                       float* __restrict__ cs, float* __restrict__ part,
                                       int tid) {
    constexpr int P    = (THREADS / C) < 8 ? (THREADS / C) : 8;
    constexpr int ROWS = (NODES + P - 1) / P;
    if (tid < C * P) {
        int c = tid % C, p = tid / C;
        int r0 = p * ROWS;
        int r1 = (r0 + ROWS < NODES) ? (r0 + ROWS) : NODES;
        float s = 0.f;
        for (int r = r0; r < r1; r++) s += S[r * STRIDE + off + c];
        part[p * C + c] = s;
    }
    __syncthreads();
    if (tid < C) {
        float s = 0.f;
        #pragma unroll
        for (int p = 0; p < P; p++) s += part[p * C + tid];
        cs[tid] = s;
    }
    __syncthreads();
}

// GCN layer: D[n][j] = act( b[j] + sum_k ((cs[k]-S[n][k])/127) * W[k][j] )
// 2 threads per node, each computes OUT/2 channels.
template<int IN, int OUT, bool RELU>
__device__ __forceinline__ void gcn_layer(const float* __restrict__ S, float* __restrict__ D,
                                          const float* __restrict__ W, const float* __restrict__ bias,
                                          const float* __restrict__ cs, int n, int half) {
    constexpr int JT = OUT / 2;
    const int j0 = half * JT;
    float acc[JT];
    #pragma unroll
    for (int j = 0; j < JT; j++) acc[j] = bias[j0 + j];
    const float* srow = S + n * STRIDE;
    for (int k = 0; k < IN; k++) {
        float a = (cs[k] - srow[k]) * INV127;
        const float4* wr = reinterpret_cast<const float4*>(W + k * OUT + j0);
        #pragma unroll
        for (int q = 0; q < JT / 4; q++) {
            float4 w = wr[q];
            acc[4*q+0] += a * w.x;
            acc[4*q+1] += a * w.y;
            acc[4*q+2] += a * w.z;
            acc[4*q+3] += a * w.w;
        }
    }
    float* drow = D + n * STRIDE + j0;
    #pragma unroll
    for (int j = 0; j < JT; j++) drow[j] = RELU ? fmaxf(acc[j], 0.f) : acc[j];
}

__global__ __launch_bounds__(THREADS, 1)
void gnn_scene_kernel(const float* __restrict__ obj_info,
                      const float* __restrict__ W1, const float* __restrict__ b1,
                      const float* __restrict__ W2, const float* __restrict__ b2,
                      const float* __restrict__ W3, const float* __restrict__ b3,
                      const float* __restrict__ W4, const float* __restrict__ b4,
                      const float* __restrict__ Wn, const float* __restrict__ bn,
                      const float* __restrict__ Wg1, const float* __restrict__ bg1,
                      const float* __restrict__ Wg2, const float* __restrict__ bg2,
                      float* __restrict__ out) {
    extern __shared__ float sm[];
    const int tid  = threadIdx.x;
    const int b    = blockIdx.x;
    const int n    = tid & (NODES - 1);
    const int half = tid >> 7;

    // ---- load weights into smem ----
    #define CPY(dst_off, src, cnt) \
        for (int i = tid; i < (cnt); i += THREADS) sm[(dst_off) + i] = src[i];
    CPY(S_W1,  W1,  5*64);   CPY(S_B1,  b1,  64);
    CPY(S_W2,  W2,  75*64);  CPY(S_B2,  b2,  64);
    CPY(S_W3,  W3,  64*32);  CPY(S_B3,  b3,  32);
    CPY(S_W4,  W4,  32*16);  CPY(S_B4,  b4,  16);
    CPY(S_WN,  Wn,  16*2);   CPY(S_BN,  bn,  2);
    CPY(S_WG1, Wg1, 16*8);   CPY(S_BG1, bg1, 8);
    CPY(S_WG2, Wg2, 8);      CPY(S_BG2, bg2, 1);
    #undef CPY

    // ---- load info[b] into A cols 64..74 ----
    {
        const float* src = obj_info + (size_t)b * NODES * 11;
        for (int i = tid; i < NODES * 11; i += THREADS) {
            int r = i / 11, c = i % 11;
            sm[S_A + r * STRIDE + 64 + c] = src[i];
        }
    }
    __syncthreads();

    float* A    = sm + S_A;
    float* Bb   = sm + S_BUF;
    float* cs   = sm + S_CS;
    float* part = sm + S_PART;

    // ---- edge layer: S5 = colsum(info[:, :5]) ----
    colsum<5>(A, 64, cs, part, tid);

    // h1[n] = relu( ((S5 - 128*info_n[:5])/127) @ W1 + b1 ) -> A cols 0..63
    {
        constexpr int JT = 32;
        const int j0 = half * JT;
        float acc[JT];
        #pragma unroll
        for (int j = 0; j < JT; j++) acc[j] = sm[S_B1 + j0 + j];
        const float* irow = A + n * STRIDE + 64;
        #pragma unroll
        for (int k = 0; k < 5; k++) {
            float a = (cs[k] - 128.0f * irow[k]) * INV127;
            const float4* wr = reinterpret_cast<const float4*>(sm + S_W1 + k * 64 + j0);
            #pragma unroll
            for (int q = 0; q < JT / 4; q++) {
                float4 w = wr[q];
                acc[4*q+0] += a * w.x;
                acc[4*q+1] += a * w.y;
                acc[4*q+2] += a * w.z;
                acc[4*q+3] += a * w.w;
            }
        }
        float* drow = A + n * STRIDE + j0;
        #pragma unroll
        for (int j = 0; j < JT; j++) drow[j] = fmaxf(acc[j], 0.f);
    }
    __syncthreads();

    // ---- layer 2: h75 (A cols 0..74) -> h2 (Bb cols 0..63) ----
    colsum<75>(A, 0, cs, part, tid);
    gcn_layer<75, 64, true>(A, Bb, sm + S_W2, sm + S_B2, cs, n, half);
    __syncthreads();

    // ---- layer 3: h2 -> h3 (A cols 0..31) ----
    colsum<64>(Bb, 0, cs, part, tid);
    gcn_layer<64, 32, true>(Bb, A, sm + S_W3, sm + S_B3, cs, n, half);
    __syncthreads();

    // ---- layer 4: h3 -> h4 (Bb cols 0..15) ----
    colsum<32>(A, 0, cs, part, tid);
    gcn_layer<32, 16, true>(A, Bb, sm + S_W4, sm + S_B4, cs, n, half);
    __syncthreads();

    // ---- final scene sum of h4 ----
    colsum<16>(Bb, 0, cs, part, tid);

    // node classifier: agg(h4) @ Wn + bn (no relu). Each thread: one of 2 outputs.
    {
        const int j = half;
        float acc = sm[S_BN + j];
        const float* srow = Bb + n * STRIDE;
        #pragma unroll
        for (int k = 0; k < 16; k++) {
            float a = (cs[k] - srow[k]) * INV127;
            acc += a * sm[S_WN + k * 2 + j];
        }
        out[64 + ((size_t)b * NODES + n) * 2 + j] = acc;
    }

    // scene classifier: mean(h4) -> 8 -> 1 -> sigmoid. One thread.
    if (tid == 0) {
        float scene[16];
        #pragma unroll
        for (int k = 0; k < 16; k++) scene[k] = cs[k] * (1.0f / NODES);
        float z = sm[S_BG2];
        #pragma unroll
        for (int o = 0; o < 8; o++) {
            float g = sm[S_BG1 + o];
            #pragma unroll
            for (int k = 0; k < 16; k++) g += scene[k] * sm[S_WG1 + k * 8 + o];
            g = fmaxf(g, 0.f);
            z += g * sm[S_WG2 + o];
        }
        out[b] = 1.0f / (1.0f + expf(-z));
    }
}

extern "C" void kernel_launch(void* const* d_in, const int* in_sizes, int n_in,
                              void* d_out, int out_size) {
    const float* obj = (const float*)d_in[0];
    const float* W1  = (const float*)d_in[1];
    const float* b1  = (const float*)d_in[2];
    const float* W2  = (const float*)d_in[3];
    const float* b2  = (const float*)d_in[4];
    const float* W3  = (const float*)d_in[5];
    const float* b3  = (const float*)d_in[6];
    const float* W4  = (const float*)d_in[7];
    const float* b4  = (const float*)d_in[8];
    const float* Wn  = (const float*)d_in[9];
    const float* bn  = (const float*)d_in[10];
    const float* Wg1 = (const float*)d_in[11];
    const float* bg1 = (const float*)d_in[12];
    const float* Wg2 = (const float*)d_in[13];
    const float* bg2 = (const float*)d_in[14];
    // d_in[15]=src, d_in[16]=dst: complete graph, structure exploited analytically.

    cudaFuncSetAttribute(gnn_scene_kernel,
                         cudaFuncAttributeMaxDynamicSharedMemorySize, SMEM_BYTES);
    gnn_scene_kernel<<<SCENES, THREADS, SMEM_BYTES>>>(
        obj, W1, b1, W2, b2, W3, b3, W4, b4, Wn, bn, Wg1, bg1, Wg2, bg2,
        (float*)d_out);
}

// round 2
// speedup vs baseline: 1.0984x; 1.0984x over previous
#include <cuda_runtime.h>
#include <math.h>
#include <stdint.h>

// GNN on complete per-scene digraphs: B=64 scenes, N=128 nodes.
// Complete-graph identity: segment_mean at node d = (scene_sum(h) - h[d]) / 127.
// Edge layer: (S5 - 128*info_d)/127.
// R2: 2-CTA cluster per scene (128 CTAs), 64 nodes/CTA, 4 threads/node.
// Scene sums = local colsum + cluster.sync + DSMEM add of peer partial.

#define NODES    128
#define LOCALN   64
#define SCENES   64
#define THREADS  256
#define STRIDE   77         // coprime with 32 banks -> conflict-free column access
#define INV127   (1.0f/127.0f)

// smem layout (floats)
#define S_W1   0            // 5*64
#define S_B1   320
#define S_W2   384          // 75*64
#define S_B2   5184
#define S_W3   5248         // 64*32
#define S_B3   7296
#define S_W4   7328         // 32*16
#define S_B4   7840
#define S_WN   7856         // 16*2
#define S_BN   7888         // 2 (+2 pad)
#define S_WG1  7892         // 16*8
#define S_BG1  8020
#define S_WG2  8028
#define S_BG2  8036         // 1 (+3 pad)
#define S_A    8040         // 64*77 buffer A
#define S_BUF  (S_A + LOCALN*STRIDE)     // 12968
#define S_CS   (S_BUF + LOCALN*STRIDE)   // 17896 combined sums (80)
#define S_CSL  (S_CS + 80)               // 17976 local partial sums, 2 slots x 80
#define S_PART (S_CSL + 160)             // 18136 stage-1 partials (640)
#define S_TOT  (S_PART + 640)            // 18776 floats
#define SMEM_BYTES (S_TOT * 4)           // 75104 B

__device__ __forceinline__ uint32_t smem_u32(const void* p) {
    uint32_t a;
    asm("{ .reg .u64 t; cvta.to.shared.u64 t, %1; cvt.u32.u64 %0, t; }"
        : "=r"(a) : "l"(p));
    return a;
}

__device__ __forceinline__ float ld_peer_f32(uint32_t local_addr, uint32_t peer_rank) {
    uint32_t remote;
    asm("mapa.shared::cluster.u32 %0, %1, %2;"
        : "=r"(remote) : "r"(local_addr), "r"(peer_rank));
    float v;
    asm volatile("ld.shared::cluster.f32 %0, [%1];" : "=f"(v) : "r"(remote));
    return v;
}

#define CLUSTER_SYNC() do { \
    asm volatile("barrier.cluster.arrive.aligned;" ::: "memory"); \
    asm volatile("barrier.cluster.wait.aligned;"   ::: "memory"); \
} while (0)

// Stage-1+2 local column sum over LOCALN rows of C columns at 'off' -> dst[C].
// All THREADS must reach the __syncthreads.
template<int C>
__device__ __forceinline__ void colsum_local(const float* __restrict__ S, int off,
                                             float* __restrict__ dst,
                                             float* __restrict__ part, int tid) {
    constexpr int P    = (THREADS / C) < 8 ? (THREADS / C) : 8;
    constexpr int ROWS = (LOCALN + P - 1) / P;
    if (tid < C * P) {
        int c = tid % C, p = tid / C;
        int r0 = p * ROWS;
        int r1 = (r0 + ROWS < LOCALN) ? (r0 + ROWS) : LOCALN;
        float s = 0.f;
        for (int r = r0; r < r1; r++) s += S[r * STRIDE + off + c];
        part[p * C + c] = s;
    }
    __syncthreads();
    if (tid < C) {
        float s = 0.f;
        #pragma unroll
        for (int p = 0; p < P; p++) s += part[p * C + tid];
        dst[tid] = s;
    }
    // no trailing __syncthreads: caller's CLUSTER_SYNC barriers the CTA too
}

// Local colsum + cross-CTA combine into sm[S_CS..S_CS+C).
template<int C>
__device__ __forceinline__ void colsum_combined(float* __restrict__ sm,
                                                const float* __restrict__ S, int off,
                                                int slot, int tid, uint32_t peer,
                                                uint32_t smbase) {
    colsum_local<C>(S, off, sm + S_CSL + slot * 80, sm + S_PART, tid);
    CLUSTER_SYNC();
    if (tid < C) {
        uint32_t la = smbase + (uint32_t)(S_CSL + slot * 80 + tid) * 4u;
        sm[S_CS + tid] = sm[S_CSL + slot * 80 + tid] + ld_peer_f32(la, peer);
    }
    __syncthreads();
}

// GCN layer for local rows: D[n][j] = act( b[j] + sum_k ((cs[k]-S[n][k])/127) * W[k][j] )
// 4 threads per node; each computes OUT/4 channels.
template<int IN, int OUT, bool RELU>
__device__ __forceinline__ void gcn_layer(const float* __restrict__ S, float* __restrict__ D,
                                          const float* __restrict__ W, const float* __restrict__ bias,
                                          const float* __restrict__ cs, int n, int q) {
    constexpr int JT = OUT / 4;
    const int j0 = q * JT;
    float acc[JT];
    #pragma unroll
    for (int j = 0; j < JT; j++) acc[j] = bias[j0 + j];
    const float* srow = S + n * STRIDE;
    for (int k = 0; k < IN; k++) {
        float a = (cs[k] - srow[k]) * INV127;
        const float4* wr = reinterpret_cast<const float4*>(W + k * OUT + j0);
        #pragma unroll
        for (int v = 0; v < JT / 4; v++) {
            float4 w = wr[v];
            acc[4*v+0] += a * w.x;
            acc[4*v+1] += a * w.y;
            acc[4*v+2] += a * w.z;
            acc[4*v+3] += a * w.w;
        }
    }
    float* drow = D + n * STRIDE + j0;
    #pragma unroll
    for (int j = 0; j < JT; j++) drow[j] = RELU ? fmaxf(acc[j], 0.f) : acc[j];
}

__global__ __launch_bounds__(THREADS, 1) __cluster_dims__(2, 1, 1)
void gnn_scene_kernel(const float* __restrict__ obj_info,
                      const float* __restrict__ W1, const float* __restrict__ b1,
                      const float* __restrict__ W2, const float* __restrict__ b2,
                      const float* __restrict__ W3, const float* __restrict__ b3,
                      const float* __restrict__ W4, const float* __restrict__ b4,
                      const float* __restrict__ Wn, const float* __restrict__ bn,
                      const float* __restrict__ Wg1, const float* __restrict__ bg1,
                      const float* __restrict__ Wg2, const float* __restrict__ bg2,
                      float* __restrict__ out) {
    extern __shared__ float sm[];
    const int tid  = threadIdx.x;
    const int b    = blockIdx.x >> 1;
    const uint32_t rank = blockIdx.x & 1;
    const uint32_t peer = rank ^ 1u;
    const int n = tid & (LOCALN - 1);   // local node 0..63
    const int q = tid >> 6;             // quarter 0..3
    const uint32_t smbase = smem_u32(sm);

    // ---- load weights into smem ----
    #define CPY(dst_off, src, cnt) \
        for (int i = tid; i < (cnt); i += THREADS) sm[(dst_off) + i] = src[i];
    CPY(S_W1,  W1,  5*64);   CPY(S_B1,  b1,  64);
    CPY(S_W2,  W2,  75*64);  CPY(S_B2,  b2,  64);
    CPY(S_W3,  W3,  64*32);  CPY(S_B3,  b3,  32);
    CPY(S_W4,  W4,  32*16);  CPY(S_B4,  b4,  16);
    CPY(S_WN,  Wn,  16*2);   CPY(S_BN,  bn,  2);
    CPY(S_WG1, Wg1, 16*8);   CPY(S_BG1, bg1, 8);
    CPY(S_WG2, Wg2, 8);      CPY(S_BG2, bg2, 1);
    #undef CPY

    // ---- load this CTA's 64 rows of info[b] into A cols 64..74 ----
    {
        const float* src = obj_info + ((size_t)b * NODES + rank * LOCALN) * 11;
        for (int i = tid; i < LOCALN * 11; i += THREADS) {
            int r = i / 11, c = i % 11;
            sm[S_A + r * STRIDE + 64 + c] = src[i];
        }
    }
    __syncthreads();

    float* A  = sm + S_A;
    float* Bb = sm + S_BUF;
    float* cs = sm + S_CS;

    // ---- edge layer: S5 = scene colsum of info[:, :5] ----
    colsum_combined<5>(sm, A, 64, /*slot=*/0, tid, peer, smbase);

    // h1[n] = relu( ((S5 - 128*info_n[:5])/127) @ W1 + b1 ) -> A cols 0..63
    {
        constexpr int JT = 16;
        const int j0 = q * JT;
        float acc[JT];
        #pragma unroll
        for (int j = 0; j < JT; j++) acc[j] = sm[S_B1 + j0 + j];
        const float* irow = A + n * STRIDE + 64;
        #pragma unroll
        for (int k = 0; k < 5; k++) {
            float a = (cs[k] - 128.0f * irow[k]) * INV127;
            const float4* wr = reinterpret_cast<const float4*>(sm + S_W1 + k * 64 + j0);
            #pragma unroll
            for (int v = 0; v < JT / 4; v++) {
                float4 w = wr[v];
                acc[4*v+0] += a * w.x;
                acc[4*v+1] += a * w.y;
                acc[4*v+2] += a * w.z;
                acc[4*v+3] += a * w.w;
            }
        }
        float* drow = A + n * STRIDE + j0;
        #pragma unroll
        for (int j = 0; j < JT; j++) drow[j] = fmaxf(acc[j], 0.f);
    }
    __syncthreads();

    // ---- layer 2: h75 (A cols 0..74) -> h2 (Bb cols 0..63) ----
    colsum_combined<75>(sm, A, 0, /*slot=*/1, tid, peer, smbase);
    gcn_layer<75, 64, true>(A, Bb, sm + S_W2, sm + S_B2, cs, n, q);
    __syncthreads();

    // ---- layer 3: h2 -> h3 (A cols 0..31) ----
    colsum_combined<64>(sm, Bb, 0, /*slot=*/0, tid, peer, smbase);
    gcn_layer<64, 32, true>(Bb, A, sm + S_W3, sm + S_B3, cs, n, q);
    __syncthreads();

    // ---- layer 4: h3 -> h4 (Bb cols 0..15) ----
    colsum_combined<32>(sm, A, 0, /*slot=*/1, tid, peer, smbase);
    gcn_layer<32, 16, true>(A, Bb, sm + S_W4, sm + S_B4, cs, n, q);
    __syncthreads();

    // ---- final scene sum of h4 ----
    colsum_combined<16>(sm, Bb, 0, /*slot=*/0, tid, peer, smbase);

    // node classifier: two threads/node write j=0,1 (no relu)
    if (q < 2) {
        const int j = q;
        float acc = sm[S_BN + j];
        const float* srow = Bb + n * STRIDE;
        #pragma unroll
        for (int k = 0; k < 16; k++) {
            float a = (cs[k] - srow[k]) * INV127;
            acc += a * sm[S_WN + k * 2 + j];
        }
        size_t gnode = (size_t)b * NODES + rank * LOCALN + n;
        out[64 + gnode * 2 + j] = acc;
    }

    // scene classifier on combined cs: rank 0, thread 0
    if (rank == 0 && tid == 0) {
        float scene[16];
        #pragma unroll
        for (int k = 0; k < 16; k++) scene[k] = cs[k] * (1.0f / NODES);
        float z = sm[S_BG2];
        #pragma unroll
        for (int o = 0; o < 8; o++) {
            float g = sm[S_BG1 + o];
            #pragma unroll
            for (int k = 0; k < 16; k++) g += scene[k] * sm[S_WG1 + k * 8 + o];
            g = fmaxf(g, 0.f);
            z += g * sm[S_WG2 + o];
        }
        out[b] = 1.0f / (1.0f + expf(-z));
    }

    // no CTA may exit while the peer might still read its csl via DSMEM:
    CLUSTER_SYNC();
}

extern "C" void kernel_launch(void* const* d_in, const int* in_sizes, int n_in,
                              void* d_out, int out_size) {
    const float* obj = (const float*)d_in[0];
    const float* W1  = (const float*)d_in[1];
    const float* b1  = (const float*)d_in[2];
    const float* W2  = (const float*)d_in[3];
    const float* b2  = (const float*)d_in[4];
    const float* W3  = (const float*)d_in[5];
    const float* b3  = (const float*)d_in[6];
    const float* W4  = (const float*)d_in[7];
    const float* b4  = (const float*)d_in[8];
    const float* Wn  = (const float*)d_in[9];
    const float* bn  = (const float*)d_in[10];
    const float* Wg1 = (const float*)d_in[11];
    const float* bg1 = (const float*)d_in[12];
    const float* Wg2 = (const float*)d_in[13];
    const float* bg2 = (const float*)d_in[14];
    // d_in[15]=src, d_in[16]=dst: complete graph, exploited analytically.

    cudaFuncSetAttribute(gnn_scene_kernel,
                         cudaFuncAttributeMaxDynamicSharedMemorySize, SMEM_BYTES);
    gnn_scene_kernel<<<SCENES * 2, THREADS, SMEM_BYTES>>>(
        obj, W1, b1, W2, b2, W3, b3, W4, b4, Wn, bn, Wg1, bg1, Wg2, bg2,
        (float*)d_out);
}

// round 4
// speedup vs baseline: 1.2706x; 1.1568x over previous
#include <cuda_runtime.h>
#include <math.h>
#include <stdint.h>

// GNN on complete per-scene digraphs: B=64 scenes, N=128 nodes.
// segment_mean at node d = (scene_sum(h) - h[d]) / 127.
// R4: 2-CTA cluster per scene, 512 thr/CTA (8 thr/node). Cluster latency
// hidden behind node-term FMAs via base-partial split:
//   out = relu(b + cs@Ws - s@Ws),  base = b + bp_local + bp_peer.
// Fix vs R3: nodeterm JT=2 instantiation computed nothing (JT/4==0);
// now handled via float2 path.

#define NODES    128
#define LOCALN   64
#define SCENES   64
#define THREADS  512
#define STRIDE   77          // coprime with 32 -> conflict-free column access
#define INV127   (1.0f/127.0f)

// smem layout (floats)
#define S_W1s    0           // 5*64   (W1/127)
#define S_W1s128 320         // 5*64   (W1*128/127)
#define S_B1     640         // 64
#define S_W2s    704         // 75*64
#define S_B2     5504        // 64
#define S_W3s    5568        // 64*32
#define S_B3     7616        // 32
#define S_W4s    7648        // 32*16
#define S_B4     8160        // 16
#define S_WNs    8176        // 16*2
#define S_BN     8208        // 2 (+2 pad)
#define S_WG1    8212        // 16*8
#define S_BG1    8340        // 8
#define S_WG2    8348        // 8
#define S_BG2    8356        // 1 (+3 pad)
#define S_A      8360        // 64*77
#define S_BUF    (S_A + LOCALN*STRIDE)    // 13288
#define S_CSL    (S_BUF + LOCALN*STRIDE)  // 18216: 2 slots x 80 local colsums
#define S_BP     (S_CSL + 160)            // 18376: 2 slots x 64 base-partials
#define S_BASE   (S_BP + 128)             // 18504: 64
#define S_PART   (S_BASE + 64)            // 18568: 512
#define S_TOT    (S_PART + 512)           // 19080
#define SMEM_BYTES (S_TOT * 4)            // 76320 B

__device__ __forceinline__ uint32_t smem_u32(const void* p) {
    uint32_t a;
    asm("{ .reg .u64 t; cvta.to.shared.u64 t, %1; cvt.u32.u64 %0, t; }"
        : "=r"(a) : "l"(p));
    return a;
}
__device__ __forceinline__ float ld_peer_f32(uint32_t local_addr, uint32_t peer_rank) {
    uint32_t remote;
    asm("mapa.shared::cluster.u32 %0, %1, %2;"
        : "=r"(remote) : "r"(local_addr), "r"(peer_rank));
    float v;
    asm volatile("ld.shared::cluster.f32 %0, [%1];" : "=f"(v) : "r"(remote));
    return v;
}
#define CLUSTER_ARRIVE() asm volatile("barrier.cluster.arrive.aligned;" ::: "memory")
#define CLUSTER_WAIT()   asm volatile("barrier.cluster.wait.aligned;"   ::: "memory")

// local column sum over LOCALN rows of C columns at 'off' -> dst[C].
template<int C>
__device__ __forceinline__ void colsum_local(const float* __restrict__ S, int off,
                                             float* __restrict__ dst,
                                             float* __restrict__ part, int tid) {
    constexpr int P    = (THREADS / C) < 16 ? (THREADS / C) : 16;
    constexpr int ROWS = (LOCALN + P - 1) / P;
    if (tid < C * P) {
        int c = tid % C, p = tid / C;
        int r0 = p * ROWS;
        int r1 = (r0 + ROWS < LOCALN) ? (r0 + ROWS) : LOCALN;
        float s = 0.f;
        for (int r = r0; r < r1; r++) s += S[r * STRIDE + off + c];
        part[p * C + c] = s;
    }
    __syncthreads();
    if (tid < C) {
        float s = 0.f;
        #pragma unroll
        for (int p = 0; p < P; p++) s += part[p * C + tid];
        dst[tid] = s;
    }
    __syncthreads();   // csl visible to base-partial readers
}

// base-partial: bp[j] = sum_k csl[k] * Ws[k*OUT+j], 4 threads per j.
template<int OUT, int IN>
__device__ __forceinline__ void basepart(const float* __restrict__ csl,
                                         const float* __restrict__ Ws,
                                         float* __restrict__ bp, int tid) {
    if (tid < 4 * OUT) {
        const int j = tid >> 2, p = tid & 3;
        float s = 0.f;
        for (int k = p; k < IN; k += 4) s += csl[k] * Ws[k * OUT + j];
        const unsigned m = (4 * OUT >= 32) ? 0xffffffffu : ((1u << (4 * OUT)) - 1u);
        s += __shfl_xor_sync(m, s, 1);
        s += __shfl_xor_sync(m, s, 2);
        if (p == 0) bp[j] = s;
    }
}

// node term: acc[j] = sum_k S[n][k+off] * Ws[k*OUT + q*JT + j]
template<int IN, int OUT, int JT>
__device__ __forceinline__ void nodeterm(const float* __restrict__ S, int off,
                                         const float* __restrict__ Ws,
                                         float* __restrict__ acc, int n, int q) {
    const int j0 = q * JT;
    #pragma unroll
    for (int j = 0; j < JT; j++) acc[j] = 0.f;
    const float* srow = S + n * STRIDE + off;
    if constexpr ((JT & 3) == 0) {
        for (int k = 0; k < IN; k++) {
            float a = srow[k];
            const float4* wr = reinterpret_cast<const float4*>(Ws + k * OUT + j0);
            #pragma unroll
            for (int v = 0; v < JT / 4; v++) {
                float4 w = wr[v];
                acc[4*v+0] += a * w.x;
                acc[4*v+1] += a * w.y;
                acc[4*v+2] += a * w.z;
                acc[4*v+3] += a * w.w;
            }
        }
    } else if constexpr (JT == 2) {
        for (int k = 0; k < IN; k++) {
            float a = srow[k];
            float2 w = *reinterpret_cast<const float2*>(Ws + k * OUT + j0);
            acc[0] += a * w.x;
            acc[1] += a * w.y;
        }
    } else {
        for (int k = 0; k < IN; k++) {
            float a = srow[k];
            #pragma unroll
            for (int j = 0; j < JT; j++) acc[j] += a * Ws[k * OUT + j0 + j];
        }
    }
}

template<int JT, bool RELU>
__device__ __forceinline__ void emit(float* __restrict__ D, const float* __restrict__ base,
                                     const float* __restrict__ acc, int n, int q) {
    const int j0 = q * JT;
    float* drow = D + n * STRIDE + j0;
    #pragma unroll
    for (int j = 0; j < JT; j++) {
        float v = base[j0 + j] - acc[j];
        drow[j] = RELU ? fmaxf(v, 0.f) : v;
    }
}

__global__ __launch_bounds__(THREADS, 1) __cluster_dims__(2, 1, 1)
void gnn_scene_kernel(const float* __restrict__ obj_info,
                      const float* __restrict__ W1, const float* __restrict__ b1,
                      const float* __restrict__ W2, const float* __restrict__ b2,
                      const float* __restrict__ W3, const float* __restrict__ b3,
                      const float* __restrict__ W4, const float* __restrict__ b4,
                      const float* __restrict__ Wn, const float* __restrict__ bn,
                      const float* __restrict__ Wg1, const float* __restrict__ bg1,
                      const float* __restrict__ Wg2, const float* __restrict__ bg2,
                      float* __restrict__ out) {
    extern __shared__ float sm[];
    const int tid  = threadIdx.x;
    const int b    = blockIdx.x >> 1;
    const uint32_t rank = blockIdx.x & 1;
    const uint32_t peer = rank ^ 1u;
    const int n = tid & (LOCALN - 1);   // local node 0..63
    const int q = tid >> 6;             // eighth 0..7
    const uint32_t smbase = smem_u32(sm);

    // ---- load + prescale weights ----
    for (int i = tid; i < 5 * 64; i += THREADS) {
        float w = W1[i];
        sm[S_W1s + i]    = w * INV127;
        sm[S_W1s128 + i] = w * (128.0f * INV127);
    }
    #define CPYS(dst, src, cnt) \
        for (int i = tid; i < (cnt); i += THREADS) sm[(dst) + i] = src[i] * INV127;
    #define CPY(dst, src, cnt) \
        for (int i = tid; i < (cnt); i += THREADS) sm[(dst) + i] = src[i];
    CPYS(S_W2s, W2, 75*64);  CPY(S_B2, b2, 64);
    CPYS(S_W3s, W3, 64*32);  CPY(S_B3, b3, 32);
    CPYS(S_W4s, W4, 32*16);  CPY(S_B4, b4, 16);
    CPYS(S_WNs, Wn, 16*2);   CPY(S_BN, bn, 2);
    CPY(S_B1, b1, 64);
    CPY(S_WG1, Wg1, 16*8);   CPY(S_BG1, bg1, 8);
    CPY(S_WG2, Wg2, 8);      CPY(S_BG2, bg2, 1);
    #undef CPYS
    #undef CPY

    // ---- load this CTA's 64 rows of info[b] into A cols 64..74 ----
    {
        const float* src = obj_info + ((size_t)b * NODES + rank * LOCALN) * 11;
        for (int i = tid; i < LOCALN * 11; i += THREADS) {
            int r = i / 11, c = i % 11;
            sm[S_A + r * STRIDE + 64 + c] = src[i];
        }
    }
    __syncthreads();

    float* A    = sm + S_A;
    float* Bb   = sm + S_BUF;
    float* part = sm + S_PART;
    float* base = sm + S_BASE;

    float acc[8];

    // ============ layer 1 (edge): info[:, :5] -> h1 (A cols 0..63) ============
    {
        const int slot = 0;
        float* csl = sm + S_CSL + slot * 80;
        float* bp  = sm + S_BP  + slot * 64;
        colsum_local<5>(A, 64, csl, part, tid);
        basepart<64, 5>(csl, sm + S_W1s, bp, tid);
        CLUSTER_ARRIVE();
        nodeterm<5, 64, 8>(A, 64, sm + S_W1s128, acc, n, q);
        CLUSTER_WAIT();
        if (tid < 64) {
            uint32_t la = smbase + (uint32_t)(S_BP + slot * 64 + tid) * 4u;
            base[tid] = sm[S_B1 + tid] + bp[tid] + ld_peer_f32(la, peer);
        }
        __syncthreads();
        emit<8, true>(A, base, acc, n, q);
        __syncthreads();
    }

    // ============ layer 2: h75 (A cols 0..74) -> h2 (Bb cols 0..63) ============
    {
        const int slot = 1;
        float* csl = sm + S_CSL + slot * 80;
        float* bp  = sm + S_BP  + slot * 64;
        colsum_local<75>(A, 0, csl, part, tid);
        basepart<64, 75>(csl, sm + S_W2s, bp, tid);
        CLUSTER_ARRIVE();
        nodeterm<75, 64, 8>(A, 0, sm + S_W2s, acc, n, q);
        CLUSTER_WAIT();
        if (tid < 64) {
            uint32_t la = smbase + (uint32_t)(S_BP + slot * 64 + tid) * 4u;
            base[tid] = sm[S_B2 + tid] + bp[tid] + ld_peer_f32(la, peer);
        }
        __syncthreads();
        emit<8, true>(Bb, base, acc, n, q);
        __syncthreads();
    }

    // ============ layer 3: h2 -> h3 (A cols 0..31) ============
    {
        const int slot = 0;
        float* csl = sm + S_CSL + slot * 80;
        float* bp  = sm + S_BP  + slot * 64;
        colsum_local<64>(Bb, 0, csl, part, tid);
        basepart<32, 64>(csl, sm + S_W3s, bp, tid);
        CLUSTER_ARRIVE();
        nodeterm<64, 32, 4>(Bb, 0, sm + S_W3s, acc, n, q);
        CLUSTER_WAIT();
        if (tid < 32) {
            uint32_t la = smbase + (uint32_t)(S_BP + slot * 64 + tid) * 4u;
            base[tid] = sm[S_B3 + tid] + bp[tid] + ld_peer_f32(la, peer);
        }
        __syncthreads();
        emit<4, true>(A, base, acc, n, q);
        __syncthreads();
    }

    // ============ layer 4: h3 -> h4 (Bb cols 0..15) ============
    {
        const int slot = 1;
        float* csl = sm + S_CSL + slot * 80;
        float* bp  = sm + S_BP  + slot * 64;
        colsum_local<32>(A, 0, csl, part, tid);
        basepart<16, 32>(csl, sm + S_W4s, bp, tid);
        CLUSTER_ARRIVE();
        nodeterm<32, 16, 2>(A, 0, sm + S_W4s, acc, n, q);
        CLUSTER_WAIT();
        if (tid < 16) {
            uint32_t la = smbase + (uint32_t)(S_BP + slot * 64 + tid) * 4u;
            base[tid] = sm[S_B4 + tid] + bp[tid] + ld_peer_f32(la, peer);
        }
        __syncthreads();
        emit<2, true>(Bb, base, acc, n, q);
        __syncthreads();
    }

    // ============ node + scene heads on h4 (Bb cols 0..15) ============
    {
        const int slot = 0;
        float* csl = sm + S_CSL + slot * 80;
        float* bp  = sm + S_BP  + slot * 64;
        colsum_local<16>(Bb, 0, csl, part, tid);
        basepart<2, 16>(csl, sm + S_WNs, bp, tid);
        CLUSTER_ARRIVE();
        float accn = 0.f;
        if (q < 2) {
            const float* srow = Bb + n * STRIDE;
            #pragma unroll
            for (int k = 0; k < 16; k++) accn += srow[k] * sm[S_WNs + k * 2 + q];
        }
        CLUSTER_WAIT();
        if (tid < 2) {
            uint32_t la = smbase + (uint32_t)(S_BP + slot * 64 + tid) * 4u;
            base[tid] = sm[S_BN + tid] + bp[tid] + ld_peer_f32(la, peer);
        }
        __syncthreads();
        if (q < 2) {
            size_t gnode = (size_t)b * NODES + rank * LOCALN + n;
            out[64 + gnode * 2 + q] = base[q] - accn;
        }

        // scene classifier: rank 0, thread 0; cs16 = csl + peer csl
        if (rank == 0 && tid == 0) {
            float scene[16];
            #pragma unroll
            for (int k = 0; k < 16; k++) {
                uint32_t la = smbase + (uint32_t)(S_CSL + slot * 80 + k) * 4u;
                scene[k] = (csl[k] + ld_peer_f32(la, peer)) * (1.0f / NODES);
            }
            float z = sm[S_BG2];
            #pragma unroll
            for (int o = 0; o < 8; o++) {
                float g = sm[S_BG1 + o];
                #pragma unroll
                for (int k = 0; k < 16; k++) g += scene[k] * sm[S_WG1 + k * 8 + o];
                g = fmaxf(g, 0.f);
                z += g * sm[S_WG2 + o];
            }
            out[b] = 1.0f / (1.0f + expf(-z));
        }
    }

    // protect peer's outstanding DSMEM reads of csl/bp before exit
    CLUSTER_ARRIVE();
    CLUSTER_WAIT();
}

extern "C" void kernel_launch(void* const* d_in, const int* in_sizes, int n_in,
                              void* d_out, int out_size) {
    const float* obj = (const float*)d_in[0];
    const float* W1  = (const float*)d_in[1];
    const float* b1  = (const float*)d_in[2];
    const float* W2  = (const float*)d_in[3];
    const float* b2  = (const float*)d_in[4];
    const float* W3  = (const float*)d_in[5];
    const float* b3  = (const float*)d_in[6];
    const float* W4  = (const float*)d_in[7];
    const float* b4  = (const float*)d_in[8];
    const float* Wn  = (const float*)d_in[9];
    const float* bn  = (const float*)d_in[10];
    const float* Wg1 = (const float*)d_in[11];
    const float* bg1 = (const float*)d_in[12];
    const float* Wg2 = (const float*)d_in[13];
    const float* bg2 = (const float*)d_in[14];
    // d_in[15]=src, d_in[16]=dst: complete graph, exploited analytically.

    cudaFuncSetAttribute(gnn_scene_kernel,
                         cudaFuncAttributeMaxDynamicSharedMemorySize, SMEM_BYTES);
    gnn_scene_kernel<<<SCENES * 2, THREADS, SMEM_BYTES>>>(
        obj, W1, b1, W2, b2, W3, b3, W4, b4, Wn, bn, Wg1, bg1, Wg2, bg2,
        (float*)d_out);
}